// round 5
// baseline (speedup 1.0000x reference)
#include <cuda_runtime.h>
#include <cuda_bf16.h>
#include <math.h>
#include <stdint.h>

// Problem constants
#define BSZ  16384
#define HD   256
#define GXD  70
#define GYD  70
#define SWIN 2
#define NKW  25   // 5x5 window

// ---------------- scratch (static device memory, no allocations) ----------------
// g_AH: per row [featHi(256)|featHi|featLo | hidHi(256)|hidHi|hidLo]  (A-side pattern)
// g_W1: per new-row jn=4u+g: [ihHi|ihLo|ihHi | hhHi|hhLo|hhHi] of orig row g*256+u
// g_Waux: w_hh n-gate rows (512+u): [hi|lo|hi]
// g_Wout: per row [hi(512)|lo(512)|hi(512)]
// g_Cext: per row [mixHi(256)|qHi|mixHi|qHi|mixLo|qLo]
__device__ __align__(16) __nv_bfloat16 g_AH  [(size_t)BSZ * 1536];
__device__ __align__(16) __nv_bfloat16 g_W1  [(size_t)1024 * 1536];
__device__ __align__(16) __nv_bfloat16 g_Waux[(size_t)256 * 768];
__device__ __align__(16) __nv_bfloat16 g_Wout[(size_t)256 * 1536];
__device__ __align__(16) __nv_bfloat16 g_Cext[(size_t)BSZ * 1536];
__device__ float g_hn[(size_t)BSZ * 256];
__device__ float g_sg[(size_t)BSZ * 256];
__device__ float g_ug[(size_t)BSZ * 256];
__device__ float g_bc[1024];   // combined bias, gate-interleaved order

__device__ __forceinline__ float sigmoidf_(float x) {
    return 1.0f / (1.0f + expf(-x));
}

__device__ __forceinline__ uint32_t smem_u32(const void* p) {
    uint32_t a;
    asm("{ .reg .u64 t; cvta.to.shared.u64 t, %1; cvt.u32.u64 %0, t; }" : "=r"(a) : "l"(p));
    return a;
}

__device__ __forceinline__ void ldsm_x4(uint32_t addr, uint32_t& r0, uint32_t& r1,
                                        uint32_t& r2, uint32_t& r3) {
    asm volatile("ldmatrix.sync.aligned.m8n8.x4.shared.b16 {%0,%1,%2,%3}, [%4];"
                 : "=r"(r0), "=r"(r1), "=r"(r2), "=r"(r3) : "r"(addr));
}

__device__ __forceinline__ void mma16816(float& d0, float& d1, float& d2, float& d3,
                                         uint32_t a0, uint32_t a1, uint32_t a2, uint32_t a3,
                                         uint32_t b0, uint32_t b1) {
    asm volatile("mma.sync.aligned.m16n8k16.row.col.f32.bf16.bf16.f32 "
                 "{%0,%1,%2,%3}, {%4,%5,%6,%7}, {%8,%9}, {%0,%1,%2,%3};"
                 : "+f"(d0), "+f"(d1), "+f"(d2), "+f"(d3)
                 : "r"(a0), "r"(a1), "r"(a2), "r"(a3), "r"(b0), "r"(b1));
}

#define CP_ASYNC16(dst, src) \
    asm volatile("cp.async.cg.shared.global [%0], [%1], 16;" :: "r"(dst), "l"(src))
#define CP_COMMIT() asm volatile("cp.async.commit_group;")
#define CP_WAIT1()  asm volatile("cp.async.wait_group 1;")

// Swizzled tile: 128 rows x 128B (64 bf16), unit' = unit ^ (row&7). 16KB/tile.
#define TILEB   16384
#define STAGEB  32768   // A tile + B tile
#define NSTAGE  3
#define SMEM_BYTES (NSTAGE * STAGEB)

// ---------------- conversion kernels -------------------------------------------
__global__ __launch_bounds__(256) void conv_ah_kernel(const float* __restrict__ input_tensor,
                                                      const float* __restrict__ hidden) {
    size_t i = (size_t)blockIdx.x * 256 + threadIdx.x;   // BSZ*128 threads, 2 cols each
    size_t b = i >> 7;
    int c = (int)(i & 127) * 2;
    const float* src; int stride, base;
    if (blockIdx.z == 0) { src = input_tensor; stride = 258; base = 0; }
    else                 { src = hidden;       stride = 256; base = 768; }
    float2 v = *(const float2*)(src + b * stride + c);
    __nv_bfloat16 h0 = __float2bfloat16(v.x);
    __nv_bfloat16 h1 = __float2bfloat16(v.y);
    __nv_bfloat16 l0 = __float2bfloat16(v.x - __bfloat162float(h0));
    __nv_bfloat16 l1 = __float2bfloat16(v.y - __bfloat162float(h1));
    __nv_bfloat162 hh; hh.x = h0; hh.y = h1;
    __nv_bfloat162 ll; ll.x = l0; ll.y = l1;
    __nv_bfloat16* d = g_AH + b * 1536 + base + c;
    *(__nv_bfloat162*)(d)       = hh;
    *(__nv_bfloat162*)(d + 256) = hh;
    *(__nv_bfloat162*)(d + 512) = ll;
}

__global__ __launch_bounds__(256) void conv_w_kernel(const float* __restrict__ w_ih,
                                                     const float* __restrict__ w_hh,
                                                     const float* __restrict__ w_out) {
    const int sel = blockIdx.z;
    size_t e = ((size_t)blockIdx.x * 256 + threadIdx.x) * 2;
    const float* src; __nv_bfloat16* dst;
    if (sel <= 1) {                       // g_W1 halves, gate-interleaved rows
        if (blockIdx.x >= 512) return;
        int rn = (int)(e >> 8), k = (int)(e & 255);
        int orig = (rn & 3) * 256 + (rn >> 2);
        src = ((sel == 0) ? w_ih : w_hh) + (size_t)orig * 256 + k;
        dst = g_W1 + (size_t)rn * 1536 + (sel ? 768 : 0) + k;
        float2 v = *(const float2*)src;
        __nv_bfloat16 h0 = __float2bfloat16(v.x), h1 = __float2bfloat16(v.y);
        __nv_bfloat16 l0 = __float2bfloat16(v.x - __bfloat162float(h0));
        __nv_bfloat16 l1 = __float2bfloat16(v.y - __bfloat162float(h1));
        __nv_bfloat162 hh; hh.x = h0; hh.y = h1;
        __nv_bfloat162 ll; ll.x = l0; ll.y = l1;
        *(__nv_bfloat162*)(dst)       = hh;
        *(__nv_bfloat162*)(dst + 256) = ll;
        *(__nv_bfloat162*)(dst + 512) = hh;
    } else if (sel == 2) {                // g_Wout from w_out (256 x 512)
        if (blockIdx.x >= 256) return;
        int r = (int)(e >> 9), k = (int)(e & 511);
        float2 v = *(const float2*)(w_out + (size_t)r * 512 + k);
        __nv_bfloat16 h0 = __float2bfloat16(v.x), h1 = __float2bfloat16(v.y);
        __nv_bfloat16 l0 = __float2bfloat16(v.x - __bfloat162float(h0));
        __nv_bfloat16 l1 = __float2bfloat16(v.y - __bfloat162float(h1));
        __nv_bfloat162 hh; hh.x = h0; hh.y = h1;
        __nv_bfloat162 ll; ll.x = l0; ll.y = l1;
        __nv_bfloat16* d = g_Wout + (size_t)r * 1536 + k;
        *(__nv_bfloat162*)(d)        = hh;
        *(__nv_bfloat162*)(d + 512)  = ll;
        *(__nv_bfloat162*)(d + 1024) = hh;
    } else {                              // g_Waux from w_hh n-gate rows
        if (blockIdx.x >= 128) return;
        int u = (int)(e >> 8), k = (int)(e & 255);
        float2 v = *(const float2*)(w_hh + (size_t)(512 + u) * 256 + k);
        __nv_bfloat16 h0 = __float2bfloat16(v.x), h1 = __float2bfloat16(v.y);
        __nv_bfloat16 l0 = __float2bfloat16(v.x - __bfloat162float(h0));
        __nv_bfloat16 l1 = __float2bfloat16(v.y - __bfloat162float(h1));
        __nv_bfloat162 hh; hh.x = h0; hh.y = h1;
        __nv_bfloat162 ll; ll.x = l0; ll.y = l1;
        __nv_bfloat16* d = g_Waux + (size_t)u * 768 + k;
        *(__nv_bfloat162*)(d)       = hh;
        *(__nv_bfloat162*)(d + 256) = ll;
        *(__nv_bfloat162*)(d + 512) = hh;
    }
}

__global__ void conv_bias_kernel(const float* __restrict__ b_ih,
                                 const float* __restrict__ b_hh) {
    int jn = blockIdx.x * 256 + threadIdx.x;
    int orig = (jn & 3) * 256 + (jn >> 2);
    g_bc[jn] = b_ih[orig] + b_hh[orig];
}

// ---------------- pipelined mma.sync GEMM mainloop ------------------------------
// acc[mt][nt][4]: warp tile 32(m) x 64(n); 8 warps in 4(m) x 2(n). One sync/chunk.
template <int KEXT>
__device__ __forceinline__ void mma_gemm_main(const __nv_bfloat16* __restrict__ A, int lda,
                                              const __nv_bfloat16* __restrict__ W, int ldw,
                                              char* smem, float (&acc)[2][8][4]) {
    const int tid = threadIdx.x;
    const int wid = tid >> 5, lane = tid & 31;
    const int wm = (wid & 3) * 32;
    const int wn = (wid >> 2) * 64;
    const uint32_t sbase = smem_u32(smem);

    const int crow0 = tid >> 3, cunit = tid & 7;
    const __nv_bfloat16* ga = A + (size_t)(blockIdx.y * 128) * lda + cunit * 8;
    const __nv_bfloat16* gw = W + (size_t)(blockIdx.x * 128) * ldw + cunit * 8;

    int rowA[2], rowB[4];
#pragma unroll
    for (int mt = 0; mt < 2; mt++)
        rowA[mt] = wm + mt * 16 + (lane & 8) + (lane & 7);
#pragma unroll
    for (int nt2 = 0; nt2 < 4; nt2++)
        rowB[nt2] = wn + nt2 * 16 + ((lane >> 4) & 1) * 8 + (lane & 7);
    const int uA = lane >> 4;
    const int uB = (lane >> 3) & 1;

    constexpr int NC = KEXT / 64;

    auto issue = [&](int ch) {
        const int s = ch % NSTAGE;
        const uint32_t dA = sbase + s * STAGEB;
        const uint32_t dB = dA + TILEB;
#pragma unroll
        for (int j = 0; j < 4; j++) {
            const int row = crow0 + j * 32;
            const uint32_t off = (uint32_t)row * 128 + (uint32_t)((cunit ^ (row & 7)) * 16);
            CP_ASYNC16(dA + off, ga + (size_t)row * lda + ch * 64);
            CP_ASYNC16(dB + off, gw + (size_t)row * ldw + ch * 64);
        }
        CP_COMMIT();
    };

    issue(0);
    issue(1);
#pragma unroll 1
    for (int ch = 0; ch < NC; ch++) {
        CP_WAIT1();            // group ch complete (committed = ch+2 here)
        __syncthreads();       // everyone done with chunk ch-1 -> stage reuse safe
        if (ch + 2 < NC) issue(ch + 2); else CP_COMMIT();
        const int s = ch % NSTAGE;
        const uint32_t aB = sbase + s * STAGEB;
        const uint32_t bB = aB + TILEB;
#pragma unroll
        for (int ks = 0; ks < 4; ks++) {
            uint32_t a[2][4], b[4][4];
#pragma unroll
            for (int mt = 0; mt < 2; mt++) {
                const int u = ks * 2 + uA;
                const uint32_t addr = aB + (uint32_t)rowA[mt] * 128
                                    + (uint32_t)((u ^ (rowA[mt] & 7)) * 16);
                ldsm_x4(addr, a[mt][0], a[mt][1], a[mt][2], a[mt][3]);
            }
#pragma unroll
            for (int nt2 = 0; nt2 < 4; nt2++) {
                const int u = ks * 2 + uB;
                const uint32_t addr = bB + (uint32_t)rowB[nt2] * 128
                                    + (uint32_t)((u ^ (rowB[nt2] & 7)) * 16);
                ldsm_x4(addr, b[nt2][0], b[nt2][1], b[nt2][2], b[nt2][3]);
            }
#pragma unroll
            for (int mt = 0; mt < 2; mt++)
#pragma unroll
                for (int nt = 0; nt < 8; nt++) {
                    const uint32_t b0 = b[nt >> 1][(nt & 1) * 2 + 0];
                    const uint32_t b1 = b[nt >> 1][(nt & 1) * 2 + 1];
                    mma16816(acc[mt][nt][0], acc[mt][nt][1], acc[mt][nt][2], acc[mt][nt][3],
                             a[mt][0], a[mt][1], a[mt][2], a[mt][3], b0, b1);
                }
        }
    }
}

// ---------------- aux GEMM: h_n = hidden @ w_hh[n]^T + b_hh[n] ------------------
__global__ __launch_bounds__(256) void aux_gemm_kernel(const float* __restrict__ b_hh) {
    extern __shared__ char smem[];
    float acc[2][8][4];
#pragma unroll
    for (int mt = 0; mt < 2; mt++)
#pragma unroll
        for (int nt = 0; nt < 8; nt++)
#pragma unroll
            for (int e = 0; e < 4; e++) acc[mt][nt][e] = 0.0f;

    mma_gemm_main<768>(g_AH + 768, 1536, g_Waux, 768, smem, acc);

    const int wid = threadIdx.x >> 5, lane = threadIdx.x & 31;
    const int wm = (wid & 3) * 32, wn = (wid >> 2) * 64;
    const int gid = lane >> 2, tig = lane & 3;
#pragma unroll
    for (int mt = 0; mt < 2; mt++) {
        const int r = blockIdx.y * 128 + wm + mt * 16 + gid;
#pragma unroll
        for (int nt = 0; nt < 8; nt++) {
            const int c = blockIdx.x * 128 + wn + nt * 8 + 2 * tig;
            float2 bv = *(const float2*)(b_hh + 512 + c);
            float2 v0 = { acc[mt][nt][0] + bv.x, acc[mt][nt][1] + bv.y };
            float2 v1 = { acc[mt][nt][2] + bv.x, acc[mt][nt][3] + bv.y };
            *(float2*)(g_hn + (size_t)r * 256 + c)       = v0;
            *(float2*)(g_hn + (size_t)(r + 8) * 256 + c) = v1;
        }
    }
}

// ---------------- main GEMM: all gate sums + fused gate math --------------------
__global__ __launch_bounds__(256) void tgemm1_kernel() {
    extern __shared__ char smem[];
    float acc[2][8][4];
#pragma unroll
    for (int mt = 0; mt < 2; mt++)
#pragma unroll
        for (int nt = 0; nt < 8; nt++)
#pragma unroll
            for (int e = 0; e < 4; e++) acc[mt][nt][e] = 0.0f;

    mma_gemm_main<1536>(g_AH, 1536, g_W1, 1536, smem, acc);
    __syncthreads();   // mainloop fully drained; smem is now free for staging

    __nv_bfloat16* qh_s = (__nv_bfloat16*)smem;          // [128][32]
    __nv_bfloat16* ql_s = qh_s + 4096;                   // [128][32]
    float* sg_s = (float*)(smem + 16384);                // [128][32]
    float* ug_s = sg_s + 4096;                           // [128][32]

    const int tid = threadIdx.x, wid = tid >> 5, lane = tid & 31;
    const int wm = (wid & 3) * 32, wn = (wid >> 2) * 64;
    const int gid = lane >> 2, tig = lane & 3;
    const int srcLane = lane & ~1;
#pragma unroll
    for (int mt = 0; mt < 2; mt++) {
#pragma unroll
        for (int nt = 0; nt < 8; nt++) {
            const int col = wn + nt * 8 + 2 * tig;         // 0..127 within tile
            const float bc0 = g_bc[blockIdx.x * 128 + col];
            const float bc1 = g_bc[blockIdx.x * 128 + col + 1];
#pragma unroll
            for (int half = 0; half < 2; half++) {
                const int rl = wm + mt * 16 + gid + half * 8;   // 0..127
                float v0 = acc[mt][nt][half * 2 + 0] + bc0;
                float v1 = acc[mt][nt][half * 2 + 1] + bc1;
                float sig0 = sigmoidf_(v0);
                float sig1 = sigmoidf_(v1);
                float rg = __shfl_sync(0xffffffffu, sig0, srcLane);
                float ug = __shfl_sync(0xffffffffu, sig1, srcLane);
                if (tig & 1) {   // holds (s_n, s_s) of unit u
                    const int ul = col >> 2;                    // 0..31
                    const size_t rg_i = (size_t)(blockIdx.y * 128 + rl) * 256
                                      + blockIdx.x * 32 + ul;
                    float hn = g_hn[rg_i];
                    float q  = tanhf(v0 + (rg - 1.0f) * hn);
                    __nv_bfloat16 qh = __float2bfloat16(q);
                    qh_s[rl * 32 + ul] = qh;
                    ql_s[rl * 32 + ul] = __float2bfloat16(q - __bfloat162float(qh));
                    sg_s[rl * 32 + ul] = sig1;   // spatialgate
                    ug_s[rl * 32 + ul] = ug;     // updategate
                }
            }
        }
    }
    __syncthreads();
    // coalesced global writes
    for (int idx = tid; idx < 4096; idx += 256) {
        const int rl = idx >> 5, ul = idx & 31;
        const size_t r = blockIdx.y * 128 + rl;
        const int u = blockIdx.x * 32 + ul;
        __nv_bfloat16 qh = qh_s[idx], ql = ql_s[idx];
        g_Cext[r * 1536 + 256 + u]  = qh;
        g_Cext[r * 1536 + 768 + u]  = qh;
        g_Cext[r * 1536 + 1280 + u] = ql;
        g_sg[r * 256 + u] = sg_s[idx];
        g_ug[r * 256 + u] = ug_s[idx];
    }
}

// ---------------- kernel: attention over 5x5 context ---------------------------
__global__ __launch_bounds__(256) void phaseB_kernel(
    const float* __restrict__ input_tensor,
    const float* __restrict__ memory) {
    const int b = blockIdx.x;
    const int t = threadIdx.x;

    __shared__ float q_s[HD];
    __shared__ float ctx[NKW][HD];
    __shared__ float attn_s[NKW];
    __shared__ float w_s[NKW];

    __nv_bfloat16* crow = g_Cext + (size_t)b * 1536;
    float q = __bfloat162float(crow[256 + t]) + __bfloat162float(crow[1280 + t]);
    q_s[t] = q;

    int gx = (int)input_tensor[(size_t)b * 258 + 256] + SWIN;
    int gy = (int)input_tensor[(size_t)b * 258 + 257] + SWIN;
    gx = min(max(gx, 0), GXD - 1);
    gy = min(max(gy, 0), GYD - 1);

#pragma unroll
    for (int k = 0; k < NKW; k++) {
        int xi = min(max(gx + k / 5 - SWIN, 0), GXD - 1);
        int yi = min(max(gy + k % 5 - SWIN, 0), GYD - 1);
        ctx[k][t] = __ldg(&memory[((size_t)xi * GYD + yi) * HD + t]);
    }
    __syncthreads();

    const int lane = t & 31, wrp = t >> 5;
    for (int k = wrp; k < NKW; k += 8) {
        float sum = 0.0f;
#pragma unroll
        for (int e = 0; e < 8; e++)
            sum += q_s[lane + e * 32] * ctx[k][lane + e * 32];
#pragma unroll
        for (int off = 16; off; off >>= 1)
            sum += __shfl_xor_sync(0xffffffffu, sum, off);
        if (lane == 0) attn_s[k] = sum;
    }
    __syncthreads();

    if (t < 32) {
        float v = (lane < NKW) ? attn_s[lane] : -INFINITY;
        if (v == 0.0f) v = -INFINITY;
        float mx = v;
#pragma unroll
        for (int off = 16; off; off >>= 1)
            mx = fmaxf(mx, __shfl_xor_sync(0xffffffffu, mx, off));
        float e = (mx == -INFINITY) ? 0.0f : expf(v - mx);
        float den = e;
#pragma unroll
        for (int off = 16; off; off >>= 1)
            den += __shfl_xor_sync(0xffffffffu, den, off);
        float wv = (den > 0.0f) ? (e / den) : 0.0f;
        if (lane < NKW) w_s[lane] = wv;
    }
    __syncthreads();

    float mix = 0.0f;
#pragma unroll
    for (int k = 0; k < NKW; k++)
        mix = fmaf(w_s[k], ctx[k][t], mix);

    __nv_bfloat16 mh = __float2bfloat16(mix);
    __nv_bfloat16 ml = __float2bfloat16(mix - __bfloat162float(mh));
    crow[t]        = mh;
    crow[512 + t]  = mh;
    crow[1024 + t] = ml;
}

// ---------------- kernel: output GEMM + fused GRU epilogue ----------------------
__global__ __launch_bounds__(256) void tgemm2_kernel(const float* __restrict__ b_out,
                                                     const float* __restrict__ hidden,
                                                     float* __restrict__ out) {
    extern __shared__ char smem[];
    float acc[2][8][4];
#pragma unroll
    for (int mt = 0; mt < 2; mt++)
#pragma unroll
        for (int nt = 0; nt < 8; nt++)
#pragma unroll
            for (int e = 0; e < 4; e++) acc[mt][nt][e] = 0.0f;

    mma_gemm_main<1536>(g_Cext, 1536, g_Wout, 1536, smem, acc);

    const int wid = threadIdx.x >> 5, lane = threadIdx.x & 31;
    const int wm = (wid & 3) * 32, wn = (wid >> 2) * 64;
    const int gid = lane >> 2, tig = lane & 3;
#pragma unroll
    for (int mt = 0; mt < 2; mt++) {
        const int rbase = blockIdx.y * 128 + wm + mt * 16 + gid;
#pragma unroll
        for (int nt = 0; nt < 8; nt++) {
            const int c = blockIdx.x * 128 + wn + nt * 8 + 2 * tig;
            float2 bv = *(const float2*)(b_out + c);
#pragma unroll
            for (int half = 0; half < 2; half++) {
                const int r = rbase + half * 8;
                const __nv_bfloat16* crow = g_Cext + (size_t)r * 1536;
                __nv_bfloat162 qh2 = *(const __nv_bfloat162*)(crow + 256 + c);
                __nv_bfloat162 ql2 = *(const __nv_bfloat162*)(crow + 1280 + c);
                float2 sg2 = *(const float2*)(g_sg + (size_t)r * 256 + c);
                float2 ug2 = *(const float2*)(g_ug + (size_t)r * 256 + c);
                float2 h2  = *(const float2*)(hidden + (size_t)r * 256 + c);
                float q0 = __bfloat162float(qh2.x) + __bfloat162float(ql2.x);
                float q1 = __bfloat162float(qh2.y) + __bfloat162float(ql2.y);
                float v0 = acc[mt][nt][half * 2 + 0] + bv.x;
                float v1 = acc[mt][nt][half * 2 + 1] + bv.y;
                float a0 = tanhf(v0), a1 = tanhf(v1);
                float cu0 = q0 + sg2.x * a0;
                float cu1 = q1 + sg2.y * a1;
                float2 o;
                o.x = cu0 + ug2.x * (h2.x - cu0);
                o.y = cu1 + ug2.y * (h2.y - cu1);
                *(float2*)(out + (size_t)r * 256 + c) = o;
            }
        }
    }
}

// ---------------- launch ---------------------------------------------------------
extern "C" void kernel_launch(void* const* d_in, const int* in_sizes, int n_in,
                              void* d_out, int out_size) {
    const float* input_tensor = (const float*)d_in[0];  // (B, 258)
    const float* hidden       = (const float*)d_in[1];  // (B, 256)
    const float* w_ih         = (const float*)d_in[2];  // (1024, 256)
    const float* b_ih         = (const float*)d_in[3];  // (1024)
    const float* w_hh         = (const float*)d_in[4];  // (1024, 256)
    const float* b_hh         = (const float*)d_in[5];  // (1024)
    const float* w_out        = (const float*)d_in[6];  // (256, 512)
    const float* b_out        = (const float*)d_in[7];  // (256)
    const float* memory       = (const float*)d_in[8];  // (70, 70, 256)
    float* out = (float*)d_out;                         // (B, 256)

    // Host-side, idempotent, not a stream op (capture-safe).
    cudaFuncSetAttribute(aux_gemm_kernel, cudaFuncAttributeMaxDynamicSharedMemorySize, SMEM_BYTES);
    cudaFuncSetAttribute(tgemm1_kernel,  cudaFuncAttributeMaxDynamicSharedMemorySize, SMEM_BYTES);
    cudaFuncSetAttribute(tgemm2_kernel,  cudaFuncAttributeMaxDynamicSharedMemorySize, SMEM_BYTES);

    conv_ah_kernel<<<dim3(8192, 1, 2), 256>>>(input_tensor, hidden);
    conv_w_kernel<<<dim3(512, 1, 4), 256>>>(w_ih, w_hh, w_out);
    conv_bias_kernel<<<4, 256>>>(b_ih, b_hh);
    aux_gemm_kernel<<<dim3(2, 128), 256, SMEM_BYTES>>>(b_hh);
    tgemm1_kernel<<<dim3(8, 128), 256, SMEM_BYTES>>>();
    phaseB_kernel<<<BSZ, 256>>>(input_tensor, memory);
    tgemm2_kernel<<<dim3(2, 128), 256, SMEM_BYTES>>>(b_out, hidden, out);
}

// round 6
// speedup vs baseline: 1.1768x; 1.1768x over previous
#include <cuda_runtime.h>
#include <cuda_bf16.h>
#include <math.h>
#include <stdint.h>

// Problem constants
#define BSZ  16384
#define HD   256
#define GXD  70
#define GYD  70
#define SWIN 2
#define NKW  25   // 5x5 window

// ---------------- scratch (static device memory, no allocations) ----------------
// bf16 split-extended operands: A-side layout [hi | hi | lo], W-side [hi | lo | hi]
__device__ __align__(16) __nv_bfloat16 g_Aext[(size_t)BSZ * 768];
__device__ __align__(16) __nv_bfloat16 g_Hext[(size_t)BSZ * 768];
__device__ __align__(16) __nv_bfloat16 g_Wih [(size_t)1024 * 768];
__device__ __align__(16) __nv_bfloat16 g_Whh [(size_t)1024 * 768];
__device__ __align__(16) __nv_bfloat16 g_Wout[(size_t)256 * 1536];
__device__ __align__(16) __nv_bfloat16 g_Cext[(size_t)BSZ * 1536];
__device__ float g_gi[(size_t)BSZ * 1024];
__device__ float g_gh[(size_t)BSZ * 1024];
__device__ float g_sg[(size_t)BSZ * 256];
__device__ float g_ug[(size_t)BSZ * 256];

__device__ __forceinline__ float sigmoidf_(float x) {
    return 1.0f / (1.0f + expf(-x));
}

__device__ __forceinline__ uint32_t smem_u32(const void* p) {
    uint32_t a;
    asm("{ .reg .u64 t; cvta.to.shared.u64 t, %1; cvt.u32.u64 %0, t; }" : "=r"(a) : "l"(p));
    return a;
}

__device__ __forceinline__ void ldsm_x4(uint32_t addr, uint32_t& r0, uint32_t& r1,
                                        uint32_t& r2, uint32_t& r3) {
    asm volatile("ldmatrix.sync.aligned.m8n8.x4.shared.b16 {%0,%1,%2,%3}, [%4];"
                 : "=r"(r0), "=r"(r1), "=r"(r2), "=r"(r3) : "r"(addr));
}

__device__ __forceinline__ void mma16816(float& d0, float& d1, float& d2, float& d3,
                                         uint32_t a0, uint32_t a1, uint32_t a2, uint32_t a3,
                                         uint32_t b0, uint32_t b1) {
    asm volatile("mma.sync.aligned.m16n8k16.row.col.f32.bf16.bf16.f32 "
                 "{%0,%1,%2,%3}, {%4,%5,%6,%7}, {%8,%9}, {%0,%1,%2,%3};"
                 : "+f"(d0), "+f"(d1), "+f"(d2), "+f"(d3)
                 : "r"(a0), "r"(a1), "r"(a2), "r"(a3), "r"(b0), "r"(b1));
}

#define CP_ASYNC16(dst, src) \
    asm volatile("cp.async.cg.shared.global [%0], [%1], 16;" :: "r"(dst), "l"(src))
#define CP_COMMIT() asm volatile("cp.async.commit_group;")
#define CP_WAIT2()  asm volatile("cp.async.wait_group 2;")

// Swizzled tile: 128 rows x 128B (64 bf16), unit' = unit ^ (row&7). 16KB/tile.
#define TILEB   16384
#define STAGEB  32768   // A tile + B tile
#define NSTAGE  3
#define SMEM_BYTES (NSTAGE * STAGEB)

// ---------------- conversion kernels (fp32 -> split bf16, extended K) ----------
// A-side layout per row: [hi(K) | hi(K) | lo(K)]
__global__ __launch_bounds__(256) void conv_ah_kernel(const float* __restrict__ input_tensor,
                                                      const float* __restrict__ hidden) {
    size_t i = (size_t)blockIdx.x * 256 + threadIdx.x;   // BSZ*128 threads, 2 cols each
    size_t b = i >> 7;
    int c = (int)(i & 127) * 2;
    const float* src; __nv_bfloat16* dst; int stride;
    if (blockIdx.z == 0) { src = input_tensor; dst = g_Aext; stride = 258; }
    else                 { src = hidden;       dst = g_Hext; stride = 256; }
    float2 v = *(const float2*)(src + b * stride + c);
    __nv_bfloat16 h0 = __float2bfloat16(v.x);
    __nv_bfloat16 h1 = __float2bfloat16(v.y);
    __nv_bfloat16 l0 = __float2bfloat16(v.x - __bfloat162float(h0));
    __nv_bfloat16 l1 = __float2bfloat16(v.y - __bfloat162float(h1));
    __nv_bfloat162 hh; hh.x = h0; hh.y = h1;
    __nv_bfloat162 ll; ll.x = l0; ll.y = l1;
    __nv_bfloat16* d = dst + b * 768 + c;
    *(__nv_bfloat162*)(d)       = hh;
    *(__nv_bfloat162*)(d + 256) = hh;
    *(__nv_bfloat162*)(d + 512) = ll;
}

// W-side layout per row: [hi(K) | lo(K) | hi(K)]; z selects {w_ih, w_hh, w_out}
__global__ __launch_bounds__(256) void conv_w_kernel(const float* __restrict__ w_ih,
                                                     const float* __restrict__ w_hh,
                                                     const float* __restrict__ w_out) {
    const int sel = blockIdx.z;
    const float* src = (sel == 0) ? w_ih : (sel == 1) ? w_hh : w_out;
    __nv_bfloat16* dst = (sel == 0) ? g_Wih : (sel == 1) ? g_Whh : g_Wout;
    const int K = (sel == 2) ? 512 : 256;
    const int nblk = (sel == 2) ? 256 : 512;
    if (blockIdx.x >= nblk) return;
    size_t e = ((size_t)blockIdx.x * 256 + threadIdx.x) * 2;
    size_t r = e / (size_t)K;
    int k = (int)(e % (size_t)K);
    float2 v = *(const float2*)(src + r * K + k);
    __nv_bfloat16 h0 = __float2bfloat16(v.x);
    __nv_bfloat16 h1 = __float2bfloat16(v.y);
    __nv_bfloat16 l0 = __float2bfloat16(v.x - __bfloat162float(h0));
    __nv_bfloat16 l1 = __float2bfloat16(v.y - __bfloat162float(h1));
    __nv_bfloat162 hh; hh.x = h0; hh.y = h1;
    __nv_bfloat162 ll; ll.x = l0; ll.y = l1;
    __nv_bfloat16* d = dst + r * (size_t)(3 * K) + k;
    *(__nv_bfloat162*)(d)         = hh;
    *(__nv_bfloat162*)(d + K)     = ll;
    *(__nv_bfloat162*)(d + 2 * K) = hh;
}

// ---------------- pipelined mma.sync GEMM mainloop ------------------------------
// acc[mt][nt][4]: warp tile 32(m) x 64(n); 8 warps in 4(m) x 2(n).
template <int KEXT>
__device__ __forceinline__ void mma_gemm_main(const __nv_bfloat16* __restrict__ A,
                                              const __nv_bfloat16* __restrict__ W,
                                              char* smem, float (&acc)[2][8][4]) {
    const int tid = threadIdx.x;
    const int wid = tid >> 5, lane = tid & 31;
    const int wm = (wid & 3) * 32;
    const int wn = (wid >> 2) * 64;
    const uint32_t sbase = smem_u32(smem);

    // copy mapping: thread handles unit (tid&7), rows (tid>>3)+j*32
    const int crow0 = tid >> 3, cunit = tid & 7;
    const __nv_bfloat16* ga = A + (size_t)(blockIdx.y * 128) * KEXT + cunit * 8;
    const __nv_bfloat16* gw = W + (size_t)(blockIdx.x * 128) * KEXT + cunit * 8;

    // ldmatrix row indices (fixed per fragment slot)
    int rowA[2], rowB[4];
#pragma unroll
    for (int mt = 0; mt < 2; mt++)
        rowA[mt] = wm + mt * 16 + (lane & 8) + (lane & 7);
#pragma unroll
    for (int nt2 = 0; nt2 < 4; nt2++)
        rowB[nt2] = wn + nt2 * 16 + ((lane >> 4) & 1) * 8 + (lane & 7);
    const int uA = lane >> 4;          // 0..1
    const int uB = (lane >> 3) & 1;    // 0..1

    constexpr int NC = KEXT / 64;

    auto issue = [&](int ch) {
        const int s = ch % NSTAGE;
        const uint32_t dA = sbase + s * STAGEB;
        const uint32_t dB = dA + TILEB;
#pragma unroll
        for (int j = 0; j < 4; j++) {
            const int row = crow0 + j * 32;
            const uint32_t off = (uint32_t)row * 128 + (uint32_t)((cunit ^ (row & 7)) * 16);
            const size_t gofs = (size_t)row * KEXT + ch * 64;
            CP_ASYNC16(dA + off, ga + gofs);
            CP_ASYNC16(dB + off, gw + gofs);
        }
        CP_COMMIT();
    };

    issue(0);
    issue(1);
#pragma unroll 1
    for (int ch = 0; ch < NC; ch++) {
        if (ch + 2 < NC) issue(ch + 2); else CP_COMMIT();
        CP_WAIT2();
        __syncthreads();
        const int s = ch % NSTAGE;
        const uint32_t aB = sbase + s * STAGEB;
        const uint32_t bB = aB + TILEB;
#pragma unroll
        for (int ks = 0; ks < 4; ks++) {
            uint32_t a[2][4], b[4][4];
#pragma unroll
            for (int mt = 0; mt < 2; mt++) {
                const int u = ks * 2 + uA;
                const uint32_t addr = aB + (uint32_t)rowA[mt] * 128
                                    + (uint32_t)((u ^ (rowA[mt] & 7)) * 16);
                ldsm_x4(addr, a[mt][0], a[mt][1], a[mt][2], a[mt][3]);
            }
#pragma unroll
            for (int nt2 = 0; nt2 < 4; nt2++) {
                const int u = ks * 2 + uB;
                const uint32_t addr = bB + (uint32_t)rowB[nt2] * 128
                                    + (uint32_t)((u ^ (rowB[nt2] & 7)) * 16);
                ldsm_x4(addr, b[nt2][0], b[nt2][1], b[nt2][2], b[nt2][3]);
            }
#pragma unroll
            for (int mt = 0; mt < 2; mt++)
#pragma unroll
                for (int nt = 0; nt < 8; nt++) {
                    const uint32_t b0 = b[nt >> 1][(nt & 1) * 2 + 0];
                    const uint32_t b1 = b[nt >> 1][(nt & 1) * 2 + 1];
                    mma16816(acc[mt][nt][0], acc[mt][nt][1], acc[mt][nt][2], acc[mt][nt][3],
                             a[mt][0], a[mt][1], a[mt][2], a[mt][3], b0, b1);
                }
        }
        __syncthreads();
    }
}

// ---------------- kernel: gi / gh GEMMs (z=0: feature, z=1: hidden) -------------
__global__ __launch_bounds__(256) void tgemm1_kernel(const float* __restrict__ b_ih,
                                                     const float* __restrict__ b_hh) {
    extern __shared__ char smem[];
    const __nv_bfloat16* A = blockIdx.z ? g_Hext : g_Aext;
    const __nv_bfloat16* W = blockIdx.z ? g_Whh  : g_Wih;
    const float* bias      = blockIdx.z ? b_hh   : b_ih;
    float* C               = blockIdx.z ? g_gh   : g_gi;

    float acc[2][8][4];
#pragma unroll
    for (int mt = 0; mt < 2; mt++)
#pragma unroll
        for (int nt = 0; nt < 8; nt++)
#pragma unroll
            for (int e = 0; e < 4; e++) acc[mt][nt][e] = 0.0f;

    mma_gemm_main<768>(A, W, smem, acc);

    const int wid = threadIdx.x >> 5, lane = threadIdx.x & 31;
    const int wm = (wid & 3) * 32, wn = (wid >> 2) * 64;
    const int gid = lane >> 2, tig = lane & 3;
#pragma unroll
    for (int mt = 0; mt < 2; mt++) {
        const int r = blockIdx.y * 128 + wm + mt * 16 + gid;
#pragma unroll
        for (int nt = 0; nt < 8; nt++) {
            const int c = blockIdx.x * 128 + wn + nt * 8 + 2 * tig;
            float2 bv = *(const float2*)(bias + c);
            float2 v0 = { acc[mt][nt][0] + bv.x, acc[mt][nt][1] + bv.y };
            float2 v1 = { acc[mt][nt][2] + bv.x, acc[mt][nt][3] + bv.y };
            *(float2*)(C + (size_t)r * 1024 + c)       = v0;
            *(float2*)(C + (size_t)(r + 8) * 1024 + c) = v1;
        }
    }
}

// ---------------- kernel: gates + attention over 5x5 context ------------------
// Vectorized: float4 gather fused with attention partial dot.
__global__ __launch_bounds__(256) void phaseB_kernel(
    const float* __restrict__ input_tensor,
    const float* __restrict__ memory) {
    const int b = blockIdx.x;
    const int t = threadIdx.x;

    __shared__ float q_s[HD];
    __shared__ float ctx[NKW][HD];
    __shared__ float attn_p[NKW][2];
    __shared__ float w_s[NKW];

    const float* gi = g_gi + (size_t)b * 1024;
    const float* gh = g_gh + (size_t)b * 1024;
    float i_r = gi[t],       h_r = gh[t];
    float i_i = gi[256 + t], h_i = gh[256 + t];
    float i_n = gi[512 + t], h_n = gh[512 + t];
    float i_s = gi[768 + t], h_s = gh[768 + t];

    float rg = sigmoidf_(i_r + h_r);
    float ug = sigmoidf_(i_i + h_i);
    float sg = sigmoidf_(i_s + h_s);
    float q  = tanhf(i_n + rg * h_n);
    q_s[t] = q;
    g_sg[(size_t)b * HD + t] = sg;
    g_ug[(size_t)b * HD + t] = ug;

    int gx = (int)input_tensor[(size_t)b * 258 + 256] + SWIN;
    int gy = (int)input_tensor[(size_t)b * 258 + 257] + SWIN;
    gx = min(max(gx, 0), GXD - 1);
    gy = min(max(gy, 0), GYD - 1);

    __syncthreads();   // q_s ready for the fused dot

    // fused gather + partial attention dot (float4); 64 threads per k-row
    const int kq  = t >> 6;          // 0..3 row group
    const int cq  = (t & 63) * 4;    // float4 column base
    const int lane = t & 31;
    const int sub  = (t >> 5) & 1;   // which half-warp of the 64-thread group
    float4 q4 = *(const float4*)(q_s + cq);
#pragma unroll
    for (int base = 0; base < 28; base += 4) {
        const int k = base + kq;
        if (k < NKW) {               // uniform per warp (64-thread groups)
            int xi = min(max(gx + k / 5 - SWIN, 0), GXD - 1);
            int yi = min(max(gy + k % 5 - SWIN, 0), GYD - 1);
            float4 v = *(const float4*)(memory + ((size_t)xi * GYD + yi) * HD + cq);
            *(float4*)(&ctx[k][cq]) = v;
            float part = v.x * q4.x + v.y * q4.y + v.z * q4.z + v.w * q4.w;
#pragma unroll
            for (int off = 16; off; off >>= 1)
                part += __shfl_xor_sync(0xffffffffu, part, off);
            if (lane == 0) attn_p[k][sub] = part;
        }
    }
    __syncthreads();

    // softmax over 25 (one warp), with attn==0 -> -inf and NaN -> 0 semantics
    if (t < 32) {
        float v = (lane < NKW) ? (attn_p[lane][0] + attn_p[lane][1]) : -INFINITY;
        if (v == 0.0f) v = -INFINITY;
        float mx = v;
#pragma unroll
        for (int off = 16; off; off >>= 1)
            mx = fmaxf(mx, __shfl_xor_sync(0xffffffffu, mx, off));
        float e = (mx == -INFINITY) ? 0.0f : expf(v - mx);
        float den = e;
#pragma unroll
        for (int off = 16; off; off >>= 1)
            den += __shfl_xor_sync(0xffffffffu, den, off);
        float wv = (den > 0.0f) ? (e / den) : 0.0f;
        if (lane < NKW) w_s[lane] = wv;
    }
    __syncthreads();

    // mix = sum_k w_k * ctx[k][:]
    float mix = 0.0f;
#pragma unroll
    for (int k = 0; k < NKW; k++)
        mix = fmaf(w_s[k], ctx[k][t], mix);

    // write combined = [mix | q] directly as split-extended bf16 (A-side layout)
    __nv_bfloat16 mh = __float2bfloat16(mix);
    __nv_bfloat16 ml = __float2bfloat16(mix - __bfloat162float(mh));
    __nv_bfloat16 qh = __float2bfloat16(q);
    __nv_bfloat16 ql = __float2bfloat16(q - __bfloat162float(qh));
    __nv_bfloat16* crow = g_Cext + (size_t)b * 1536;
    crow[t]          = mh;
    crow[512 + t]    = mh;
    crow[1024 + t]   = ml;
    crow[256 + t]    = qh;
    crow[768 + t]    = qh;
    crow[1280 + t]   = ql;
}

// ---------------- kernel: output GEMM + fused GRU epilogue ----------------------
__global__ __launch_bounds__(256) void tgemm2_kernel(const float* __restrict__ b_out,
                                                     const float* __restrict__ hidden,
                                                     float* __restrict__ out) {
    extern __shared__ char smem[];

    float acc[2][8][4];
#pragma unroll
    for (int mt = 0; mt < 2; mt++)
#pragma unroll
        for (int nt = 0; nt < 8; nt++)
#pragma unroll
            for (int e = 0; e < 4; e++) acc[mt][nt][e] = 0.0f;

    mma_gemm_main<1536>(g_Cext, g_Wout, smem, acc);

    const int wid = threadIdx.x >> 5, lane = threadIdx.x & 31;
    const int wm = (wid & 3) * 32, wn = (wid >> 2) * 64;
    const int gid = lane >> 2, tig = lane & 3;
#pragma unroll
    for (int mt = 0; mt < 2; mt++) {
        const int rbase = blockIdx.y * 128 + wm + mt * 16 + gid;
#pragma unroll
        for (int nt = 0; nt < 8; nt++) {
            const int c = blockIdx.x * 128 + wn + nt * 8 + 2 * tig;
            float2 bv = *(const float2*)(b_out + c);
#pragma unroll
            for (int half = 0; half < 2; half++) {
                const int r = rbase + half * 8;
                const __nv_bfloat16* crow = g_Cext + (size_t)r * 1536;
                __nv_bfloat162 qh2 = *(const __nv_bfloat162*)(crow + 256 + c);
                __nv_bfloat162 ql2 = *(const __nv_bfloat162*)(crow + 1280 + c);
                float2 sg2 = *(const float2*)(g_sg + (size_t)r * 256 + c);
                float2 ug2 = *(const float2*)(g_ug + (size_t)r * 256 + c);
                float2 h2  = *(const float2*)(hidden + (size_t)r * 256 + c);
                float q0 = __bfloat162float(qh2.x) + __bfloat162float(ql2.x);
                float q1 = __bfloat162float(qh2.y) + __bfloat162float(ql2.y);
                float v0 = acc[mt][nt][half * 2 + 0] + bv.x;
                float v1 = acc[mt][nt][half * 2 + 1] + bv.y;
                float a0 = tanhf(v0), a1 = tanhf(v1);
                float cu0 = q0 + sg2.x * a0;
                float cu1 = q1 + sg2.y * a1;
                float2 o;
                o.x = cu0 + ug2.x * (h2.x - cu0);
                o.y = cu1 + ug2.y * (h2.y - cu1);
                *(float2*)(out + (size_t)r * 256 + c) = o;
            }
        }
    }
}

// ---------------- launch ---------------------------------------------------------
extern "C" void kernel_launch(void* const* d_in, const int* in_sizes, int n_in,
                              void* d_out, int out_size) {
    const float* input_tensor = (const float*)d_in[0];  // (B, 258)
    const float* hidden       = (const float*)d_in[1];  // (B, 256)
    const float* w_ih         = (const float*)d_in[2];  // (1024, 256)
    const float* b_ih         = (const float*)d_in[3];  // (1024)
    const float* w_hh         = (const float*)d_in[4];  // (1024, 256)
    const float* b_hh         = (const float*)d_in[5];  // (1024)
    const float* w_out        = (const float*)d_in[6];  // (256, 512)
    const float* b_out        = (const float*)d_in[7];  // (256)
    const float* memory       = (const float*)d_in[8];  // (70, 70, 256)
    float* out = (float*)d_out;                         // (B, 256)

    // Host-side, idempotent, not a stream op (capture-safe).
    cudaFuncSetAttribute(tgemm1_kernel, cudaFuncAttributeMaxDynamicSharedMemorySize, SMEM_BYTES);
    cudaFuncSetAttribute(tgemm2_kernel, cudaFuncAttributeMaxDynamicSharedMemorySize, SMEM_BYTES);

    conv_ah_kernel<<<dim3(8192, 1, 2), 256>>>(input_tensor, hidden);
    conv_w_kernel<<<dim3(512, 1, 3), 256>>>(w_ih, w_hh, w_out);
    tgemm1_kernel<<<dim3(8, 128, 2), 256, SMEM_BYTES>>>(b_ih, b_hh);
    phaseB_kernel<<<BSZ, 256>>>(input_tensor, memory);
    tgemm2_kernel<<<dim3(2, 128), 256, SMEM_BYTES>>>(b_out, hidden, out);
}